// round 14
// baseline (speedup 1.0000x reference)
#include <cuda_runtime.h>
#include <cstdint>

// 26 node coordinates (compile-time __constant__ init; no runtime copy)
__constant__ float2 c_nodes[26] = {
    {0.5454545454545454f, 0.76f}, {0.6022727272727273f, 0.76f},
    {0.5454545454545454f, 0.86f}, {0.6022727272727273f, 0.86f},
    {0.4772727272727273f, 0.76f}, {0.42045454545454547f, 0.76f},
    {0.42045454545454547f, 0.86f}, {0.4772727272727273f, 0.86f},
    {0.32954545454545453f, 0.808f}, {0.42045454545454547f, 0.48f},
    {0.4772727272727273f, 0.48f}, {0.4772727272727273f, 0.38f},
    {0.42045454545454547f, 0.38f}, {0.32954545454545453f, 0.428f},
    {0.5727272727272728f, 0.62f}, {0.7613636363636364f, 0.76f},
    {0.8181818181818182f, 0.76f}, {0.8181818181818182f, 0.86f},
    {0.7613636363636364f, 0.86f}, {0.7909090909090909f, 0.62f},
    {0.9431818181818182f, 0.76f}, {1.0f, 0.76f},
    {1.0f, 0.86f}, {0.9431818181818182f, 0.86f},
    {0.9727272727272728f, 0.62f}, {0.9727272727272728f, 1.0f}
};

// Output row = 136 float2:
//   c in [0,3)->x2[c]; [3,67)->e1[c-3]; [67,69)->x2[c-64];
//   [69,133)->e2[c-69]; [133,136)->x2[c-128]
// 4 rows (one span) = 544 float2 = 17 dense 256B-aligned warp stores.
// Per (iteration K, lane), c is a COMPILE-TIME-shaped function of lane only.
// Fast path (all 8 indices of the span == 0): every emb access is row 0 at a
// fixed per-(K,lane) element -> preloaded register. Slow path = proven R13.

constexpr int THREADS = 256;          // 8 warps
constexpr int SPANS_PER_WARP = 4;     // 16 rows/warp -> 128 rows/block
constexpr int ROWS_PER_BLOCK = 128;

template<int K>
struct Geo {
    static constexpr int gs = K * 32;
    static constexpr int ra = gs / 136;
    static constexpr int rb = (gs + 31) / 136;
    static constexpr int ca = gs - 136 * ra;
    static constexpr int cb = gs - 136 * rb;
    static constexpr int split = 136 * rb - gs;
    static constexpr bool pure_e1 = (ra == rb) && (ca >= 3) && (ca + 31 < 67);
    static constexpr bool pure_e2 = (ra == rb) && (ca >= 69) && (ca + 31 < 133);
};

template<int K>
__device__ __forceinline__ int lane_c(int lane) {
    using G = Geo<K>;
    if constexpr (G::ra == G::rb) return G::ca + lane;
    else return (lane >= G::split ? G::cb : G::ca) + lane;
}

// Preload this lane's row-0 value for iteration K (emb2 = emb row 0 base)
template<int K>
__device__ __forceinline__ float2 rv_load(int lane, const float2* __restrict__ emb2) {
    int c = lane_c<K>(lane);
    int eidx = (c >= 3 && c < 67) ? c - 3 : ((c >= 69 && c < 133) ? c - 69 : 0);
    return emb2[eidx];
}

// Fast path: emb == row 0 everywhere -> register value rv
template<int K>
__device__ __forceinline__ void fast_iter(
    int lane, float2 rv,
    const float2* __restrict__ wx,     // warp's staged 4 rows (32 float2)
    float2* __restrict__ olane)
{
    using G = Geo<K>;
    float2 v;
    if constexpr (G::pure_e1 || G::pure_e2) {
        v = rv;                                         // bare STG iteration
    } else {
        int c = lane_c<K>(lane);
        const float2* xr = wx + ((G::ra == G::rb) ? G::ra
                                 : (lane >= G::split ? G::rb : G::ra)) * 8;
        if (c < 3)        v = xr[c];
        else if (c < 67)  v = rv;
        else if (c < 69)  v = xr[c - 64];
        else if (c < 133) v = rv;
        else              v = xr[c - 128];
    }
    __stcs(&olane[G::gs], v);
}

// Slow path: byte-identical logic to the R13 champion
template<int K>
__device__ __forceinline__ void slow_iter(
    int lane,
    const float2* __restrict__ e1a, const float2* __restrict__ e1b,
    const float2* __restrict__ e2a, const float2* __restrict__ e2b,
    const float2* __restrict__ wx,
    float2* __restrict__ olane)
{
    using G = Geo<K>;
    float2 v;
    if constexpr (G::ra == G::rb) {
        const float2* xa = wx + G::ra * 8;
        if constexpr (G::pure_e1)      v = e1a[G::ca - 3 + lane];
        else if constexpr (G::pure_e2) v = e2a[G::ca - 69 + lane];
        else {
            int c = G::ca + lane;
            if (c < 3)        v = xa[c];
            else if (c < 67)  v = e1a[c - 3];
            else if (c < 69)  v = xa[c - 64];
            else if (c < 133) v = e2a[c - 69];
            else              v = xa[c - 128];
        }
    } else {
        bool hi = lane >= G::split;
        int c = (hi ? G::cb : G::ca) + lane;
        const float2* e1 = hi ? e1b : e1a;
        const float2* e2 = hi ? e2b : e2a;
        const float2* xr = wx + (hi ? G::rb : G::ra) * 8;
        if (c < 3)        v = xr[c];
        else if (c < 67)  v = e1[c - 3];
        else if (c < 69)  v = xr[c - 64];
        else if (c < 133) v = e2[c - 69];
        else              v = xr[c - 128];
    }
    __stcs(&olane[G::gs], v);
}

__global__ __launch_bounds__(THREADS, 4) void pe_kernel(
    const float* __restrict__ x,
    const float* __restrict__ emb,
    float* __restrict__ out,
    int rows)
{
    __shared__ float2 sx2[THREADS];              // 32 float2 per warp slice

    int block_row0 = blockIdx.x * ROWS_PER_BLOCK;
    int t = threadIdx.x;
    int warp = t >> 5;
    int lane = t & 31;

    const float2* emb2 = reinterpret_cast<const float2*>(emb);
    const float2* x2g  = reinterpret_cast<const float2*>(x);
    float2* wslot = &sx2[t];
    const float2* wx = sx2 + warp * 32;

    bool active = lane < 26;
    float nx = 0.f, ny = 0.f, txl = -1.f, tyl = -1.f;
    if (active) {
        float2 n = c_nodes[lane];
        nx = n.x; ny = n.y;
        txl = 0.01f + 1e-5f * fabsf(nx);
        tyl = 0.01f + 1e-5f * fabsf(ny);
    }

    // Preload this lane's 17 row-0 emb values (reused across all 4 spans)
    float2 rv[17];
    rv[0]=rv_load<0>(lane,emb2);   rv[1]=rv_load<1>(lane,emb2);
    rv[2]=rv_load<2>(lane,emb2);   rv[3]=rv_load<3>(lane,emb2);
    rv[4]=rv_load<4>(lane,emb2);   rv[5]=rv_load<5>(lane,emb2);
    rv[6]=rv_load<6>(lane,emb2);   rv[7]=rv_load<7>(lane,emb2);
    rv[8]=rv_load<8>(lane,emb2);   rv[9]=rv_load<9>(lane,emb2);
    rv[10]=rv_load<10>(lane,emb2); rv[11]=rv_load<11>(lane,emb2);
    rv[12]=rv_load<12>(lane,emb2); rv[13]=rv_load<13>(lane,emb2);
    rv[14]=rv_load<14>(lane,emb2); rv[15]=rv_load<15>(lane,emb2);
    rv[16]=rv_load<16>(lane,emb2);

    #pragma unroll 1
    for (int s = 0; s < SPANS_PER_WARP; s++) {
        int r0 = warp * (SPANS_PER_WARP * 4) + s * 4;       // within block
        size_t grow0 = (size_t)(block_row0 + r0);

        // Warp-local stage of this span's 4 rows (dense 256B LDG)
        *wslot = x2g[grow0 * 8 + lane];
        __syncwarp();

        // Ballots for the 4 rows
        unsigned ball = 0;
        int idx1[4], idx2[4];
        #pragma unroll
        for (int rr = 0; rr < 4; rr++) {
            float2 pt1 = wx[rr * 8 + 2];
            float2 pt2 = wx[rr * 8 + 4];
            bool m1 = active && (fabsf(pt1.x - nx) <= txl) && (fabsf(pt1.y - ny) <= tyl);
            bool m2 = active && (fabsf(pt2.x - nx) <= txl) && (fabsf(pt2.y - ny) <= tyl);
            unsigned b1 = __ballot_sync(0xffffffffu, m1);
            unsigned b2 = __ballot_sync(0xffffffffu, m2);
            ball |= b1 | b2;
            idx1[rr] = __ffs(b1);       // 1-based ffs == argmax+1; 0 if none
            idx2[rr] = __ffs(b2);
        }

        float2* olane = reinterpret_cast<float2*>(out) + grow0 * 136 + lane;

        if (ball == 0) {
            // Fast path (~98.7% of spans): emb == row 0 everywhere
            fast_iter<0>(lane, rv[0], wx, olane);   fast_iter<1>(lane, rv[1], wx, olane);
            fast_iter<2>(lane, rv[2], wx, olane);   fast_iter<3>(lane, rv[3], wx, olane);
            fast_iter<4>(lane, rv[4], wx, olane);   fast_iter<5>(lane, rv[5], wx, olane);
            fast_iter<6>(lane, rv[6], wx, olane);   fast_iter<7>(lane, rv[7], wx, olane);
            fast_iter<8>(lane, rv[8], wx, olane);   fast_iter<9>(lane, rv[9], wx, olane);
            fast_iter<10>(lane, rv[10], wx, olane); fast_iter<11>(lane, rv[11], wx, olane);
            fast_iter<12>(lane, rv[12], wx, olane); fast_iter<13>(lane, rv[13], wx, olane);
            fast_iter<14>(lane, rv[14], wx, olane); fast_iter<15>(lane, rv[15], wx, olane);
            fast_iter<16>(lane, rv[16], wx, olane);
        } else {
            const float2* e1p[4];
            const float2* e2p[4];
            #pragma unroll
            for (int rr = 0; rr < 4; rr++) {
                e1p[rr] = emb2 + (size_t)idx1[rr] * 64;
                e2p[rr] = emb2 + (size_t)idx2[rr] * 64;
            }
#define ITER(K) slow_iter<K>(lane, \
            e1p[(K*32)/136], e1p[((K*32)+31)/136], \
            e2p[(K*32)/136], e2p[((K*32)+31)/136], wx, olane)
            ITER(0);  ITER(1);  ITER(2);  ITER(3);  ITER(4);  ITER(5);
            ITER(6);  ITER(7);  ITER(8);  ITER(9);  ITER(10); ITER(11);
            ITER(12); ITER(13); ITER(14); ITER(15); ITER(16);
#undef ITER
        }
        __syncwarp();   // span's LDS complete before next restage
    }
}

extern "C" void kernel_launch(void* const* d_in, const int* in_sizes, int n_in,
                              void* d_out, int out_size)
{
    const float* x;
    const float* emb;
    int xsz;
    if (in_sizes[0] > in_sizes[1]) {
        x = (const float*)d_in[0]; emb = (const float*)d_in[1]; xsz = in_sizes[0];
    } else {
        x = (const float*)d_in[1]; emb = (const float*)d_in[0]; xsz = in_sizes[1];
    }
    int rows = xsz / 16;                                       // 262144
    int blocks = (rows + ROWS_PER_BLOCK - 1) / ROWS_PER_BLOCK; // 2048 (exact)
    pe_kernel<<<blocks, THREADS>>>(x, emb, (float*)d_out, rows);
}

// round 15
// speedup vs baseline: 1.0099x; 1.0099x over previous
#include <cuda_runtime.h>
#include <cstdint>

// 26 node coordinates (compile-time __constant__ init; no runtime copy)
__constant__ float2 c_nodes[26] = {
    {0.5454545454545454f, 0.76f}, {0.6022727272727273f, 0.76f},
    {0.5454545454545454f, 0.86f}, {0.6022727272727273f, 0.86f},
    {0.4772727272727273f, 0.76f}, {0.42045454545454547f, 0.76f},
    {0.42045454545454547f, 0.86f}, {0.4772727272727273f, 0.86f},
    {0.32954545454545453f, 0.808f}, {0.42045454545454547f, 0.48f},
    {0.4772727272727273f, 0.48f}, {0.4772727272727273f, 0.38f},
    {0.42045454545454547f, 0.38f}, {0.32954545454545453f, 0.428f},
    {0.5727272727272728f, 0.62f}, {0.7613636363636364f, 0.76f},
    {0.8181818181818182f, 0.76f}, {0.8181818181818182f, 0.86f},
    {0.7613636363636364f, 0.86f}, {0.7909090909090909f, 0.62f},
    {0.9431818181818182f, 0.76f}, {1.0f, 0.76f},
    {1.0f, 0.86f}, {0.9431818181818182f, 0.86f},
    {0.9727272727272728f, 0.62f}, {0.9727272727272728f, 1.0f}
};

// Output row = 136 float2:
//   c in [0,3)->x2[c]; [3,67)->e1[c-3]; [67,69)->x2[c-64];
//   [69,133)->e2[c-69]; [133,136)->x2[c-128]
// One span = 4 rows = 544 float2 = 17 dense 256B-aligned warp stores.
// x staging is REGISTER-ONLY: lane L holds float2 L of the span (x2 element
// (row, j) lives in lane row*8+j); points and x-sourced output elements come
// via __shfl_sync. No smem, no barriers. 2 spans per warp, x LDGs front-issued.

constexpr int THREADS = 512;          // 16 warps
constexpr int ROWS_PER_BLOCK = 128;   // 16 warps x 2 spans x 4 rows

template<int K>
__device__ __forceinline__ void do_iter(
    int lane, float2 mx,              // this lane's x float2 of the span
    const float2* __restrict__ e1a, const float2* __restrict__ e1b,
    const float2* __restrict__ e2a, const float2* __restrict__ e2b,
    float2* __restrict__ olane)
{
    constexpr int gs = K * 32;
    constexpr int ra = gs / 136;
    constexpr int rb = (gs + 31) / 136;
    constexpr int ca = gs - 136 * ra;
    float2 v;
    if constexpr (ra == rb && ca >= 3 && ca + 31 < 67) {
        v = e1a[ca - 3 + lane];                        // pure e1: bare LDG
    } else if constexpr (ra == rb && ca >= 69 && ca + 31 < 133) {
        v = e2a[ca - 69 + lane];                       // pure e2: bare LDG
    } else {
        int rr, c;
        const float2* e1;
        const float2* e2;
        if constexpr (ra == rb) {
            rr = ra; c = ca + lane; e1 = e1a; e2 = e2a;
        } else {
            constexpr int split = 136 * rb - gs;       // 8, 16 or 24
            constexpr int cb = gs - 136 * rb;
            bool hi = lane >= split;
            rr = hi ? rb : ra;
            c = (hi ? cb : ca) + lane;
            e1 = hi ? e1b : e1a;
            e2 = hi ? e2b : e2a;
        }
        bool isx = (c < 3) | (c >= 67 && c < 69) | (c >= 133);
        int xc = (c < 3) ? c : ((c < 69) ? c - 64 : c - 128);
        int srclane = rr * 8 + xc;                     // x2 element -> owning lane
        float2 xv;
        xv.x = __shfl_sync(0xffffffffu, mx.x, srclane);
        xv.y = __shfl_sync(0xffffffffu, mx.y, srclane);
        float2 ev = make_float2(0.f, 0.f);
        if (!isx) ev = (c < 67) ? e1[c - 3] : e2[c - 69];   // predicated LDG
        v = isx ? xv : ev;
    }
    __stcs(&olane[gs], v);
}

__device__ __forceinline__ void process_span(
    int lane, float2 mx, bool active,
    float nx, float ny, float txl, float tyl,
    const float2* __restrict__ emb2,
    float2* __restrict__ olane)
{
    // Ballots: points of row rr are x2 elements rr*8+2 (floats 4,5) and rr*8+4
    const float2* e1p[4];
    const float2* e2p[4];
    #pragma unroll
    for (int rr = 0; rr < 4; rr++) {
        float2 pt1, pt2;
        pt1.x = __shfl_sync(0xffffffffu, mx.x, rr * 8 + 2);
        pt1.y = __shfl_sync(0xffffffffu, mx.y, rr * 8 + 2);
        pt2.x = __shfl_sync(0xffffffffu, mx.x, rr * 8 + 4);
        pt2.y = __shfl_sync(0xffffffffu, mx.y, rr * 8 + 4);
        bool m1 = active && (fabsf(pt1.x - nx) <= txl) && (fabsf(pt1.y - ny) <= tyl);
        bool m2 = active && (fabsf(pt2.x - nx) <= txl) && (fabsf(pt2.y - ny) <= tyl);
        int idx1 = __ffs(__ballot_sync(0xffffffffu, m1));  // 1-based ffs == argmax+1
        int idx2 = __ffs(__ballot_sync(0xffffffffu, m2));
        e1p[rr] = emb2 + (size_t)idx1 * 64;
        e2p[rr] = emb2 + (size_t)idx2 * 64;
    }

#define ITER(K) do_iter<K>(lane, mx, \
        e1p[(K*32)/136], e1p[((K*32)+31)/136], \
        e2p[(K*32)/136], e2p[((K*32)+31)/136], olane)
    ITER(0);  ITER(1);  ITER(2);  ITER(3);  ITER(4);  ITER(5);
    ITER(6);  ITER(7);  ITER(8);  ITER(9);  ITER(10); ITER(11);
    ITER(12); ITER(13); ITER(14); ITER(15); ITER(16);
#undef ITER
}

__global__ __launch_bounds__(THREADS) void pe_kernel(
    const float* __restrict__ x,
    const float* __restrict__ emb,
    float* __restrict__ out,
    int rows)
{
    int t = threadIdx.x;
    int warp = t >> 5;
    int lane = t & 31;

    int block_row0 = blockIdx.x * ROWS_PER_BLOCK;
    size_t span0_row = (size_t)(block_row0 + warp * 8);        // spans are 4 rows
    size_t span1_row = span0_row + 4;

    const float2* x2g = reinterpret_cast<const float2*>(x);
    // Front-issue both spans' x loads (dense 256B LDG.64 each; MLP=2)
    float2 mx0 = x2g[span0_row * 8 + lane];
    float2 mx1 = x2g[span1_row * 8 + lane];

    bool active = lane < 26;
    float nx = 0.f, ny = 0.f, txl = -1.f, tyl = -1.f;
    if (active) {
        float2 n = c_nodes[lane];
        nx = n.x; ny = n.y;
        txl = 0.01f + 1e-5f * fabsf(nx);
        tyl = 0.01f + 1e-5f * fabsf(ny);
    }

    const float2* emb2 = reinterpret_cast<const float2*>(emb);
    float2* outf2 = reinterpret_cast<float2*>(out);

    process_span(lane, mx0, active, nx, ny, txl, tyl, emb2,
                 outf2 + span0_row * 136 + lane);
    process_span(lane, mx1, active, nx, ny, txl, tyl, emb2,
                 outf2 + span1_row * 136 + lane);
}

extern "C" void kernel_launch(void* const* d_in, const int* in_sizes, int n_in,
                              void* d_out, int out_size)
{
    const float* x;
    const float* emb;
    int xsz;
    if (in_sizes[0] > in_sizes[1]) {
        x = (const float*)d_in[0]; emb = (const float*)d_in[1]; xsz = in_sizes[0];
    } else {
        x = (const float*)d_in[1]; emb = (const float*)d_in[0]; xsz = in_sizes[1];
    }
    int rows = xsz / 16;                                       // 262144
    int blocks = (rows + ROWS_PER_BLOCK - 1) / ROWS_PER_BLOCK; // 2048 (exact)
    pe_kernel<<<blocks, THREADS>>>(x, emb, (float*)d_out, rows);
}

// round 16
// speedup vs baseline: 1.0471x; 1.0368x over previous
#include <cuda_runtime.h>
#include <cstdint>

// 26 node coordinates (compile-time __constant__ init; no runtime copy)
__constant__ float2 c_nodes[26] = {
    {0.5454545454545454f, 0.76f}, {0.6022727272727273f, 0.76f},
    {0.5454545454545454f, 0.86f}, {0.6022727272727273f, 0.86f},
    {0.4772727272727273f, 0.76f}, {0.42045454545454547f, 0.76f},
    {0.42045454545454547f, 0.86f}, {0.4772727272727273f, 0.86f},
    {0.32954545454545453f, 0.808f}, {0.42045454545454547f, 0.48f},
    {0.4772727272727273f, 0.48f}, {0.4772727272727273f, 0.38f},
    {0.42045454545454547f, 0.38f}, {0.32954545454545453f, 0.428f},
    {0.5727272727272728f, 0.62f}, {0.7613636363636364f, 0.76f},
    {0.8181818181818182f, 0.76f}, {0.8181818181818182f, 0.86f},
    {0.7613636363636364f, 0.86f}, {0.7909090909090909f, 0.62f},
    {0.9431818181818182f, 0.76f}, {1.0f, 0.76f},
    {1.0f, 0.86f}, {0.9431818181818182f, 0.86f},
    {0.9727272727272728f, 0.62f}, {0.9727272727272728f, 1.0f}
};

// Output row = 136 float2:
//   c in [0,3)->x2[c]; [3,67)->e1[c-3]; [67,69)->x2[c-64];
//   [69,133)->e2[c-69]; [133,136)->x2[c-128]
// 4 rows = 544 float2 = 17 x 256B, iterated flat: every store iteration is a
// dense 256B-aligned burst; iteration geometry is constexpr (template<K>).
// Staging is WARP-LOCAL (one dense 256B LDG per warp into its private smem
// slice, __syncwarp only — no block barrier; warps fully decoupled).
// This round: identical warp-level code to the R13 champion, but 256-thread
// CTAs (32 rows, grid 8192) for 4x finer scheduling granularity.

constexpr int THREADS = 256;         // 8 warps x 4 rows = 32 rows/block
constexpr int ROWS_PER_BLOCK = 32;

template<int K>
__device__ __forceinline__ void do_iter(
    int lane,
    const float2* __restrict__ e1a, const float2* __restrict__ e1b,
    const float2* __restrict__ e2a, const float2* __restrict__ e2b,
    const float2* __restrict__ xa,  const float2* __restrict__ xb,
    float2* __restrict__ olane)
{
    constexpr int gs = K * 32;
    constexpr int ra = gs / 136;
    constexpr int rb = (gs + 31) / 136;
    constexpr int ca = gs - 136 * ra;        // c of lane 0 on low side
    float2 v;
    if constexpr (ra == rb) {
        if constexpr (ca >= 3 && ca + 31 < 67) {
            v = e1a[ca - 3 + lane];                    // pure e1: LDG only
        } else if constexpr (ca >= 69 && ca + 31 < 133) {
            v = e2a[ca - 69 + lane];                   // pure e2: LDG only
        } else {
            int c = ca + lane;
            if (c < 3)        v = xa[c];
            else if (c < 67)  v = e1a[c - 3];
            else if (c < 69)  v = xa[c - 64];
            else if (c < 133) v = e2a[c - 69];
            else              v = xa[c - 128];
        }
    } else {
        constexpr int split = 136 * rb - gs;           // 8, 16 or 24
        constexpr int cb = gs - 136 * rb;              // negative
        bool hi = lane >= split;
        int c = (hi ? cb : ca) + lane;
        const float2* e1 = hi ? e1b : e1a;
        const float2* e2 = hi ? e2b : e2a;
        const float2* xr = hi ? xb : xa;
        if (c < 3)        v = xr[c];
        else if (c < 67)  v = e1[c - 3];
        else if (c < 69)  v = xr[c - 64];
        else if (c < 133) v = e2[c - 69];
        else              v = xr[c - 128];
    }
    __stcs(&olane[gs], v);
}

__global__ __launch_bounds__(THREADS) void pe_kernel(
    const float* __restrict__ x,
    const float* __restrict__ emb,
    float* __restrict__ out,
    int rows)
{
    __shared__ float2 sx2[THREADS];              // 32 float2 per warp slice

    int block_row0 = blockIdx.x * ROWS_PER_BLOCK;
    int t = threadIdx.x;
    int warp = t >> 5;
    int lane = t & 31;

    // Warp-local stage: each warp loads ITS OWN 4 rows (dense 256B LDG.64)
    sx2[t] = reinterpret_cast<const float2*>(x)[(size_t)block_row0 * 8 + t];
    __syncwarp();

    const float2* wx = sx2 + warp * 32;          // this warp's 4 rows (32 float2)

    bool active = lane < 26;
    float nx = 0.f, ny = 0.f, tx = -1.f, ty = -1.f;
    if (active) {
        float2 n = c_nodes[lane];
        nx = n.x; ny = n.y;
        tx = 0.01f + 1e-5f * fabsf(nx);
        ty = 0.01f + 1e-5f * fabsf(ny);
    }

    const float2* emb2 = reinterpret_cast<const float2*>(emb);

    // Ballots for 4 rows -> per-row emb pointers (uniform across warp)
    const float2* e1p[4];
    const float2* e2p[4];
    const float2* xp[4];
    #pragma unroll
    for (int rr = 0; rr < 4; rr++) {
        float2 pt1 = wx[rr * 8 + 2];             // floats 4,5 of row rr
        float2 pt2 = wx[rr * 8 + 4];             // floats 8,9
        bool m1 = active && (fabsf(pt1.x - nx) <= tx) && (fabsf(pt1.y - ny) <= ty);
        bool m2 = active && (fabsf(pt2.x - nx) <= tx) && (fabsf(pt2.y - ny) <= ty);
        int idx1 = __ffs(__ballot_sync(0xffffffffu, m1));  // 1-based == argmax+1
        int idx2 = __ffs(__ballot_sync(0xffffffffu, m2));
        e1p[rr] = emb2 + (size_t)idx1 * 64;
        e2p[rr] = emb2 + (size_t)idx2 * 64;
        xp[rr]  = wx + rr * 8;
    }

    float2* olane = reinterpret_cast<float2*>(out)
                  + (size_t)(block_row0 + warp * 4) * 136 + lane;

#define ITER(K) do_iter<K>(lane, \
        e1p[(K*32)/136], e1p[((K*32)+31)/136], \
        e2p[(K*32)/136], e2p[((K*32)+31)/136], \
        xp[(K*32)/136],  xp[((K*32)+31)/136],  olane)
    ITER(0);  ITER(1);  ITER(2);  ITER(3);  ITER(4);  ITER(5);
    ITER(6);  ITER(7);  ITER(8);  ITER(9);  ITER(10); ITER(11);
    ITER(12); ITER(13); ITER(14); ITER(15); ITER(16);
#undef ITER
}

extern "C" void kernel_launch(void* const* d_in, const int* in_sizes, int n_in,
                              void* d_out, int out_size)
{
    const float* x;
    const float* emb;
    int xsz;
    if (in_sizes[0] > in_sizes[1]) {
        x = (const float*)d_in[0]; emb = (const float*)d_in[1]; xsz = in_sizes[0];
    } else {
        x = (const float*)d_in[1]; emb = (const float*)d_in[0]; xsz = in_sizes[1];
    }
    int rows = xsz / 16;                                       // 262144
    int blocks = (rows + ROWS_PER_BLOCK - 1) / ROWS_PER_BLOCK; // 8192 (exact)
    pe_kernel<<<blocks, THREADS>>>(x, emb, (float*)d_out, rows);
}